// round 1
// baseline (speedup 1.0000x reference)
#include <cuda_runtime.h>

#define NB 4
#define NN 10000
#define NE 160000
#define NQ 256
#define ND 128
#define NM 64
#define NU 126
#define NH 128
#define NP 7
#define OUTC (NP + ND)   // 135
#define TE 64

// -------- scratch (static device globals: allocation-free) --------
__device__ float g_states[NB * NN * ND];     // 20.5 MB
__device__ float g_incoming[NB * NN * NM];   // 10.2 MB

// -------- utility kernels --------
__global__ void copy_states_kernel(const float* __restrict__ src) {
    int i = blockIdx.x * blockDim.x + threadIdx.x;
    const int n = NB * NN * ND / 4;
    if (i < n) reinterpret_cast<float4*>(g_states)[i] =
        reinterpret_cast<const float4*>(src)[i];
}

__global__ void zero_incoming_kernel() {
    int i = blockIdx.x * blockDim.x + threadIdx.x;
    const int n = NB * NN * NM / 4;
    if (i < n) reinterpret_cast<float4*>(g_incoming)[i] = make_float4(0.f, 0.f, 0.f, 0.f);
}

__global__ void init_out_kernel(const float* __restrict__ poses, float* __restrict__ out) {
    int i = blockIdx.x * blockDim.x + threadIdx.x;
    const int n = NB * NQ * OUTC;
    if (i < n) {
        int r = i / OUTC, c = i - r * OUTC;
        out[i] = (c < NP) ? poses[r * NP + c] : 0.f;
    }
}

// =====================================================================
// Edge kernel: per 64-edge tile
//   einp[64x256] (gathered) @ w1e[256x128] -> relu -> @ w2e[128x64] -> scatter
// smem layout (floats):
//   region1 [0,17152): sA[64][260] (16640)   then reused as
//                      sH[64][132] (8448) + sW2[128][68] (8704)
//   region2 [17152,21376): sW[32][132] chunk of W1
// =====================================================================
#define EDGE_SMEM_FLOATS (17152 + 4224)

__global__ __launch_bounds__(256, 2) void edge_kernel(
    const int* __restrict__ esrc, const int* __restrict__ esnk,
    const float* __restrict__ w1, const float* __restrict__ b1,
    const float* __restrict__ w2, const float* __restrict__ b2)
{
    extern __shared__ float sm[];
    float* sA  = sm;              // [64][260]
    float* sH  = sm;              // [64][132]
    float* sW2 = sm + 64 * 132;   // [128][68]
    float* sW  = sm + 17152;      // [32][132]
    __shared__ int sSrc[TE], sSnk[TE];

    const int tid = threadIdx.x;
    const int b = blockIdx.y;
    const int e0 = blockIdx.x * TE;
    const float* st = g_states + (size_t)b * NN * ND;

    if (tid < TE) { sSrc[tid] = esrc[e0 + tid]; sSnk[tid] = esnk[e0 + tid]; }
    __syncthreads();

    // gather einp: iteration e loads all 256 features of edge e (coalesced)
    {
        const int k = tid;
        const int gk = (k < ND) ? k : (k - ND);
        #pragma unroll 4
        for (int e = 0; e < TE; e++) {
            int node = (k < ND) ? sSrc[e] : sSnk[e];
            sA[e * 260 + k] = st[node * ND + gk];
        }
    }

    const int tc = tid & 15;
    const int tr = tid >> 4;

    float acc[4][8];
    #pragma unroll
    for (int i = 0; i < 4; i++)
        #pragma unroll
        for (int j = 0; j < 8; j++) acc[i][j] = 0.f;

    // GEMM1: [64x256] @ [256x128], K chunked by 32
    for (int kc = 0; kc < 8; kc++) {
        __syncthreads();
        #pragma unroll
        for (int t = 0; t < 16; t++) {
            int idx = tid + t * 256;
            int k = idx >> 7, h = idx & 127;
            sW[k * 132 + h] = w1[(kc * 32 + k) * 128 + h];
        }
        __syncthreads();
        #pragma unroll 8
        for (int kk = 0; kk < 32; kk++) {
            float4 bv0 = *(const float4*)&sW[kk * 132 + tc * 8];
            float4 bv1 = *(const float4*)&sW[kk * 132 + tc * 8 + 4];
            float bb[8] = {bv0.x, bv0.y, bv0.z, bv0.w, bv1.x, bv1.y, bv1.z, bv1.w};
            #pragma unroll
            for (int i = 0; i < 4; i++) {
                float a = sA[(tr * 4 + i) * 260 + kc * 32 + kk];
                #pragma unroll
                for (int j = 0; j < 8; j++) acc[i][j] = fmaf(a, bb[j], acc[i][j]);
            }
        }
    }
    __syncthreads();   // all reads of sA done before overwriting with sH/sW2

    // bias + relu -> sH ; load W2 -> sW2
    {
        float4 bb0 = *(const float4*)&b1[tc * 8];
        float4 bb1 = *(const float4*)&b1[tc * 8 + 4];
        float bb[8] = {bb0.x, bb0.y, bb0.z, bb0.w, bb1.x, bb1.y, bb1.z, bb1.w};
        #pragma unroll
        for (int i = 0; i < 4; i++) {
            float4 h0, h1;
            h0.x = fmaxf(acc[i][0] + bb[0], 0.f);
            h0.y = fmaxf(acc[i][1] + bb[1], 0.f);
            h0.z = fmaxf(acc[i][2] + bb[2], 0.f);
            h0.w = fmaxf(acc[i][3] + bb[3], 0.f);
            h1.x = fmaxf(acc[i][4] + bb[4], 0.f);
            h1.y = fmaxf(acc[i][5] + bb[5], 0.f);
            h1.z = fmaxf(acc[i][6] + bb[6], 0.f);
            h1.w = fmaxf(acc[i][7] + bb[7], 0.f);
            *(float4*)&sH[(tr * 4 + i) * 132 + tc * 8] = h0;
            *(float4*)&sH[(tr * 4 + i) * 132 + tc * 8 + 4] = h1;
        }
        #pragma unroll
        for (int t = 0; t < 32; t++) {
            int idx = tid + t * 256;
            int k = idx >> 6, m = idx & 63;
            sW2[k * 68 + m] = w2[idx];
        }
    }
    __syncthreads();

    // GEMM2: [64x128] @ [128x64]
    float acc2[4][4];
    #pragma unroll
    for (int i = 0; i < 4; i++)
        #pragma unroll
        for (int j = 0; j < 4; j++) acc2[i][j] = 0.f;

    #pragma unroll 8
    for (int k = 0; k < 128; k++) {
        float4 bv = *(const float4*)&sW2[k * 68 + tc * 4];
        #pragma unroll
        for (int i = 0; i < 4; i++) {
            float a = sH[(tr * 4 + i) * 132 + k];
            acc2[i][0] = fmaf(a, bv.x, acc2[i][0]);
            acc2[i][1] = fmaf(a, bv.y, acc2[i][1]);
            acc2[i][2] = fmaf(a, bv.z, acc2[i][2]);
            acc2[i][3] = fmaf(a, bv.w, acc2[i][3]);
        }
    }

    float4 bm = *(const float4*)&b2[tc * 4];
    #pragma unroll
    for (int i = 0; i < 4; i++) {
        int e = tr * 4 + i;
        float* dst = g_incoming + ((size_t)b * NN + sSnk[e]) * NM + tc * 4;
        atomicAdd(dst + 0, acc2[i][0] + bm.x);
        atomicAdd(dst + 1, acc2[i][1] + bm.y);
        atomicAdd(dst + 2, acc2[i][2] + bm.z);
        atomicAdd(dst + 3, acc2[i][3] + bm.w);
    }
}

// =====================================================================
// Node kernel: per 64-node tile
//   ninp[64x192] = [incoming | states] @ w1n[192x128] -> relu -> @ w2n[128x126]
//   states[:, 2:128] += upd   (row-exclusive, no atomics)
// smem: region1 [0,24832): sA[64][196] (12544) then sH[64][132](8448)+sW2[128][128](16384)
//       region2 [24832,29056): sW[32][132]
// =====================================================================
#define NODE_SMEM_FLOATS (24832 + 4224)

__global__ __launch_bounds__(256, 2) void node_kernel(
    const float* __restrict__ w1, const float* __restrict__ b1,
    const float* __restrict__ w2, const float* __restrict__ b2)
{
    extern __shared__ float sm[];
    float* sA  = sm;              // [64][196]
    float* sH  = sm;              // [64][132]
    float* sW2 = sm + 64 * 132;   // [128][128]
    float* sW  = sm + 24832;      // [32][132]

    const int tid = threadIdx.x;
    const int b = blockIdx.y;
    const int n0 = blockIdx.x * 64;
    float* st = g_states + (size_t)b * NN * ND;
    const float* inc = g_incoming + (size_t)b * NN * NM;

    // gather ninp
    for (int idx = tid; idx < 64 * 192; idx += 256) {
        int e = idx / 192;
        int k = idx - e * 192;
        int node = n0 + e;
        float v = 0.f;
        if (node < NN) v = (k < NM) ? inc[node * NM + k] : st[node * ND + (k - NM)];
        sA[e * 196 + k] = v;
    }

    const int tc = tid & 15;
    const int tr = tid >> 4;

    float acc[4][8];
    #pragma unroll
    for (int i = 0; i < 4; i++)
        #pragma unroll
        for (int j = 0; j < 8; j++) acc[i][j] = 0.f;

    for (int kc = 0; kc < 6; kc++) {
        __syncthreads();
        #pragma unroll
        for (int t = 0; t < 16; t++) {
            int idx = tid + t * 256;
            int k = idx >> 7, h = idx & 127;
            sW[k * 132 + h] = w1[(kc * 32 + k) * 128 + h];
        }
        __syncthreads();
        #pragma unroll 8
        for (int kk = 0; kk < 32; kk++) {
            float4 bv0 = *(const float4*)&sW[kk * 132 + tc * 8];
            float4 bv1 = *(const float4*)&sW[kk * 132 + tc * 8 + 4];
            float bb[8] = {bv0.x, bv0.y, bv0.z, bv0.w, bv1.x, bv1.y, bv1.z, bv1.w};
            #pragma unroll
            for (int i = 0; i < 4; i++) {
                float a = sA[(tr * 4 + i) * 196 + kc * 32 + kk];
                #pragma unroll
                for (int j = 0; j < 8; j++) acc[i][j] = fmaf(a, bb[j], acc[i][j]);
            }
        }
    }
    __syncthreads();

    // bias + relu -> sH ; load W2 (pad cols 126,127 with zero)
    {
        float4 bb0 = *(const float4*)&b1[tc * 8];
        float4 bb1 = *(const float4*)&b1[tc * 8 + 4];
        float bb[8] = {bb0.x, bb0.y, bb0.z, bb0.w, bb1.x, bb1.y, bb1.z, bb1.w};
        #pragma unroll
        for (int i = 0; i < 4; i++) {
            float4 h0, h1;
            h0.x = fmaxf(acc[i][0] + bb[0], 0.f);
            h0.y = fmaxf(acc[i][1] + bb[1], 0.f);
            h0.z = fmaxf(acc[i][2] + bb[2], 0.f);
            h0.w = fmaxf(acc[i][3] + bb[3], 0.f);
            h1.x = fmaxf(acc[i][4] + bb[4], 0.f);
            h1.y = fmaxf(acc[i][5] + bb[5], 0.f);
            h1.z = fmaxf(acc[i][6] + bb[6], 0.f);
            h1.w = fmaxf(acc[i][7] + bb[7], 0.f);
            *(float4*)&sH[(tr * 4 + i) * 132 + tc * 8] = h0;
            *(float4*)&sH[(tr * 4 + i) * 132 + tc * 8 + 4] = h1;
        }
        for (int idx = tid; idx < 128 * 126; idx += 256) {
            int k = idx / 126;
            int m = idx - k * 126;
            sW2[k * 128 + m] = w2[idx];
        }
        for (int k = tid; k < 128; k += 256) {
            sW2[k * 128 + 126] = 0.f;
            sW2[k * 128 + 127] = 0.f;
        }
    }
    __syncthreads();

    // GEMM2: [64x128] @ [128x128(padded from 126)]
    float acc2[4][8];
    #pragma unroll
    for (int i = 0; i < 4; i++)
        #pragma unroll
        for (int j = 0; j < 8; j++) acc2[i][j] = 0.f;

    #pragma unroll 8
    for (int k = 0; k < 128; k++) {
        float4 bv0 = *(const float4*)&sW2[k * 128 + tc * 8];
        float4 bv1 = *(const float4*)&sW2[k * 128 + tc * 8 + 4];
        float bb[8] = {bv0.x, bv0.y, bv0.z, bv0.w, bv1.x, bv1.y, bv1.z, bv1.w};
        #pragma unroll
        for (int i = 0; i < 4; i++) {
            float a = sH[(tr * 4 + i) * 132 + k];
            #pragma unroll
            for (int j = 0; j < 8; j++) acc2[i][j] = fmaf(a, bb[j], acc2[i][j]);
        }
    }

    // in-place state update (each (node, channel) owned by exactly one thread)
    #pragma unroll
    for (int i = 0; i < 4; i++) {
        int node = n0 + tr * 4 + i;
        if (node < NN) {
            float* drow = st + node * ND + (ND - NU);  // offset 2
            #pragma unroll
            for (int j = 0; j < 8; j++) {
                int c = tc * 8 + j;
                if (c < NU) drow[c] += acc2[i][j] + b2[c];
            }
        }
    }
}

// =====================================================================
// Readout: out[b,q,7+d] = sum_n attn[b,q,n] * states[b,n,d]
// split-K over n (8 splits), atomicAdd into pre-zeroed output
// smem: sAt[32][68] (2176) + sS[64][132] (8448)
// =====================================================================
#define EXT_SMEM_FLOATS (32 * 68 + 64 * 132)
#define NSPLIT 8
#define NCHUNK (NN / NSPLIT)   // 1250

__global__ __launch_bounds__(256) void extract_kernel(
    const float* __restrict__ attn, float* __restrict__ out)
{
    extern __shared__ float sm[];
    float* sAt = sm;            // [32][68]
    float* sS  = sm + 32 * 68;  // [64][132]

    const int tid = threadIdx.x;
    const int b = blockIdx.z, qt = blockIdx.y, ns = blockIdx.x;
    const int q0 = qt * 32;
    const int nbeg = ns * NCHUNK;
    const int nend = nbeg + NCHUNK;
    const float* st = g_states + (size_t)b * NN * ND;
    const float* at = attn + ((size_t)b * NQ + q0) * NN;

    const int tc = tid & 15;
    const int tr = tid >> 4;

    float acc[2][8];
    #pragma unroll
    for (int i = 0; i < 2; i++)
        #pragma unroll
        for (int j = 0; j < 8; j++) acc[i][j] = 0.f;

    for (int n0 = nbeg; n0 < nend; n0 += 64) {
        __syncthreads();
        #pragma unroll
        for (int t = 0; t < 8; t++) {
            int idx = tid + t * 256;
            int q = idx >> 6, nn = idx & 63;
            int n = n0 + nn;
            sAt[q * 68 + nn] = (n < nend) ? at[q * NN + n] : 0.f;
        }
        #pragma unroll
        for (int t = 0; t < 32; t++) {
            int idx = tid + t * 256;
            int nn = idx >> 7, d = idx & 127;
            int n = n0 + nn;
            sS[nn * 132 + d] = (n < nend) ? st[n * ND + d] : 0.f;
        }
        __syncthreads();
        #pragma unroll 8
        for (int nn = 0; nn < 64; nn++) {
            float4 bv0 = *(const float4*)&sS[nn * 132 + tc * 8];
            float4 bv1 = *(const float4*)&sS[nn * 132 + tc * 8 + 4];
            float bb[8] = {bv0.x, bv0.y, bv0.z, bv0.w, bv1.x, bv1.y, bv1.z, bv1.w};
            float a0 = sAt[(tr * 2 + 0) * 68 + nn];
            float a1 = sAt[(tr * 2 + 1) * 68 + nn];
            #pragma unroll
            for (int j = 0; j < 8; j++) {
                acc[0][j] = fmaf(a0, bb[j], acc[0][j]);
                acc[1][j] = fmaf(a1, bb[j], acc[1][j]);
            }
        }
    }

    #pragma unroll
    for (int i = 0; i < 2; i++) {
        int q = q0 + tr * 2 + i;
        float* drow = out + ((size_t)(b * NQ + q)) * OUTC + NP + tc * 8;
        #pragma unroll
        for (int j = 0; j < 8; j++) atomicAdd(drow + j, acc[i][j]);
    }
}

// =====================================================================
extern "C" void kernel_launch(void* const* d_in, const int* in_sizes, int n_in,
                              void* d_out, int out_size)
{
    const float* nodes = (const float*)d_in[0];
    const float* poses = (const float*)d_in[1];
    const float* attn  = (const float*)d_in[2];
    const int*   esrc  = (const int*)d_in[3];
    const int*   esnk  = (const int*)d_in[4];
    const float* w1e   = (const float*)d_in[5];
    const float* b1e   = (const float*)d_in[6];
    const float* w2e   = (const float*)d_in[7];
    const float* b2e   = (const float*)d_in[8];
    const float* w1n   = (const float*)d_in[9];
    const float* b1n   = (const float*)d_in[10];
    const float* w2n   = (const float*)d_in[11];
    const float* b2n   = (const float*)d_in[12];
    float* out = (float*)d_out;

    cudaFuncSetAttribute(edge_kernel, cudaFuncAttributeMaxDynamicSharedMemorySize,
                         EDGE_SMEM_FLOATS * 4);
    cudaFuncSetAttribute(node_kernel, cudaFuncAttributeMaxDynamicSharedMemorySize,
                         NODE_SMEM_FLOATS * 4);

    copy_states_kernel<<<(NB * NN * ND / 4 + 255) / 256, 256>>>(nodes);
    for (int s = 0; s < 3; s++) {
        zero_incoming_kernel<<<(NB * NN * NM / 4 + 255) / 256, 256>>>();
        edge_kernel<<<dim3(NE / TE, NB), 256, EDGE_SMEM_FLOATS * 4>>>(
            esrc, esnk, w1e, b1e, w2e, b2e);
        node_kernel<<<dim3((NN + 63) / 64, NB), 256, NODE_SMEM_FLOATS * 4>>>(
            w1n, b1n, w2n, b2n);
    }
    init_out_kernel<<<(NB * NQ * OUTC + 255) / 256, 256>>>(poses, out);
    extract_kernel<<<dim3(NSPLIT, NQ / 32, NB), 256, EXT_SMEM_FLOATS * 4>>>(attn, out);
}

// round 3
// speedup vs baseline: 3.2327x; 3.2327x over previous
#include <cuda_runtime.h>
#include <cstdint>

#define NB 4
#define NN 10000
#define NE 160000
#define NQ 256
#define ND 128
#define NM 64
#define NU 126
#define NH 128
#define NP 7
#define OUTC (NP + ND)   // 135
#define TE 64            // edges per tile
#define NTILES_B (NE / TE)        // 2500
#define NTILES_TOT (NTILES_B * NB)
#define NT_NODE_B 157             // ceil(10000/64)
#define NT_NODE_TOT (NT_NODE_B * NB)

// -------- scratch (static device globals: allocation-free) --------
__device__ float g_states[NB * NN * ND];     // 20.5 MB
__device__ float g_incoming[NB * NN * NM];   // 10.2 MB

// ============================ helpers ============================
__device__ __forceinline__ uint32_t f2tf32(float f) {
    uint32_t r;
    asm("cvt.rna.tf32.f32 %0, %1;" : "=r"(r) : "f"(f));
    return r;
}
__device__ __forceinline__ float tf32f(float f) {
    return __uint_as_float(f2tf32(f));
}
// D += A(16x8) * B(8x8), tf32 inputs (bit patterns in b32), f32 accum
__device__ __forceinline__ void mma_tf32(float* c, uint32_t a0, uint32_t a1,
                                         uint32_t a2, uint32_t a3,
                                         uint32_t b0, uint32_t b1) {
    asm volatile(
        "mma.sync.aligned.m16n8k8.row.col.f32.tf32.tf32.f32 "
        "{%0,%1,%2,%3}, {%4,%5,%6,%7}, {%8,%9}, {%0,%1,%2,%3};"
        : "+f"(c[0]), "+f"(c[1]), "+f"(c[2]), "+f"(c[3])
        : "r"(a0), "r"(a1), "r"(a2), "r"(a3), "r"(b0), "r"(b1));
}

// -------- utility kernels --------
__global__ void copy_states_kernel(const float* __restrict__ src) {
    int i = blockIdx.x * blockDim.x + threadIdx.x;
    const int n = NB * NN * ND / 4;
    if (i < n) reinterpret_cast<float4*>(g_states)[i] =
        reinterpret_cast<const float4*>(src)[i];
}

__global__ void zero_incoming_kernel() {
    int i = blockIdx.x * blockDim.x + threadIdx.x;
    const int n = NB * NN * NM / 4;
    if (i < n) reinterpret_cast<float4*>(g_incoming)[i] = make_float4(0.f, 0.f, 0.f, 0.f);
}

__global__ void init_out_kernel(const float* __restrict__ poses, float* __restrict__ out) {
    int i = blockIdx.x * blockDim.x + threadIdx.x;
    const int n = NB * NQ * OUTC;
    if (i < n) {
        int r = i / OUTC, c = i - r * OUTC;
        out[i] = (c < NP) ? poses[r * NP + c] : 0.f;
    }
}

// =====================================================================
// Edge kernel (persistent, tf32 mma.sync)
//
// smem (floats):
//   EF_W1P [0,32768)      W1 pre-permuted frag pairs: [32 ks][16 nf][32 lane][2]
//   EF_W2P [32768,40960)  W2 pre-permuted:            [16 ks][ 8 nf][32 lane][2]
//   EF_A   [40960,45568)  gathered einp chunk, 2 bufs of [64][36]
//   EF_H   [45568,54016)  relu hidden [64][132]
//   EF_B1  54016 (128), EF_B2 54144 (64), EF_SRC 54208 (64), EF_SNK 54272 (64)
// =====================================================================
#define EF_W1P 0
#define EF_W2P 32768
#define EF_A   40960
#define EF_H   45568
#define EF_B1  54016
#define EF_B2  54144
#define EF_SRC 54208
#define EF_SNK 54272
#define EDGE_SMEM_BYTES ((54336) * 4)   // 217344

__global__ __launch_bounds__(256, 1) void edge_kernel(
    const int* __restrict__ esrc, const int* __restrict__ esnk,
    const float* __restrict__ w1, const float* __restrict__ b1,
    const float* __restrict__ w2, const float* __restrict__ b2)
{
    extern __shared__ float sf[];
    int* sSrc = (int*)(sf + EF_SRC);
    int* sSnk = (int*)(sf + EF_SNK);

    const int tid = threadIdx.x;
    const int lid = tid & 31;
    const int wid = tid >> 5;
    const int wr = wid & 3;   // edge-tile row (16 edges)
    const int wc = wid >> 2;  // column half

    // ---- stage permuted weights (once per block) ----
    for (int i = tid; i < 32 * 16 * 32; i += 256) {
        int s = i >> 9, f = (i >> 5) & 15, l = i & 31;
        int k = s * 8 + (l & 3), n = f * 8 + (l >> 2);
        float2 p;
        p.x = tf32f(w1[k * NH + n]);
        p.y = tf32f(w1[(k + 4) * NH + n]);
        *(float2*)(sf + EF_W1P + 2 * i) = p;
    }
    for (int i = tid; i < 16 * 8 * 32; i += 256) {
        int s = i >> 8, f = (i >> 5) & 7, l = i & 31;
        int k = s * 8 + (l & 3), n = f * 8 + (l >> 2);
        float2 p;
        p.x = tf32f(w2[k * NM + n]);
        p.y = tf32f(w2[(k + 4) * NM + n]);
        *(float2*)(sf + EF_W2P + 2 * i) = p;
    }
    if (tid < NH) sf[EF_B1 + tid] = b1[tid];
    if (tid < NM) sf[EF_B2 + tid] = b2[tid];
    __syncthreads();

    for (int T = blockIdx.x; T < NTILES_TOT; T += gridDim.x) {
        const int b = T / NTILES_B;
        const int e0 = (T - b * NTILES_B) * TE;
        const float* st = g_states + (size_t)b * NN * ND;
        float* inc = g_incoming + (size_t)b * NN * NM;

        if (tid < TE) sSrc[tid] = esrc[e0 + tid];
        else if (tid < 2 * TE) sSnk[tid - TE] = esnk[e0 + tid - TE];
        __syncthreads();

        float acc[8][4];
        #pragma unroll
        for (int f = 0; f < 8; f++)
            #pragma unroll
            for (int j = 0; j < 4; j++) acc[f][j] = 0.f;

        float r[8];
        // gather chunk 0 (cols 0..31, src)
        {
            const int eb = wid * 8;
            #pragma unroll
            for (int i = 0; i < 8; i++)
                r[i] = st[(size_t)sSrc[eb + i] * ND + lid];
            #pragma unroll
            for (int i = 0; i < 8; i++)
                sf[EF_A + (eb + i) * 36 + lid] = tf32f(r[i]);
        }
        __syncthreads();

        #pragma unroll 1
        for (int c = 0; c < 8; c++) {
            if (c < 7) {                       // prefetch chunk c+1
                const int cc = c + 1;
                const int* nodes = (cc < 4) ? sSrc : sSnk;
                const int gk = (cc & 3) * 32 + lid;
                #pragma unroll
                for (int i = 0; i < 8; i++)
                    r[i] = st[(size_t)nodes[wid * 8 + i] * ND + gk];
            }
            // compute chunk c (4 ksteps)
            const float* A = sf + EF_A + (c & 1) * 2304;
            const int ar = wr * 16 + (lid >> 2);
            #pragma unroll
            for (int ks = 0; ks < 4; ks++) {
                const int k = ks * 8 + (lid & 3);
                uint32_t a0 = __float_as_uint(A[ar * 36 + k]);
                uint32_t a1 = __float_as_uint(A[(ar + 8) * 36 + k]);
                uint32_t a2 = __float_as_uint(A[ar * 36 + k + 4]);
                uint32_t a3 = __float_as_uint(A[(ar + 8) * 36 + k + 4]);
                const int sg = c * 4 + ks;
                #pragma unroll
                for (int f = 0; f < 8; f++) {
                    float2 bp = *(const float2*)(sf + EF_W1P +
                        ((sg * 16 + wc * 8 + f) * 32 + lid) * 2);
                    mma_tf32(acc[f], a0, a1, a2, a3,
                             __float_as_uint(bp.x), __float_as_uint(bp.y));
                }
            }
            if (c < 7) {
                float* dst = sf + EF_A + ((c + 1) & 1) * 2304;
                #pragma unroll
                for (int i = 0; i < 8; i++)
                    dst[(wid * 8 + i) * 36 + lid] = tf32f(r[i]);
            }
            __syncthreads();
        }

        // epilogue1: bias + relu -> H (tf32)
        {
            const int r0 = wr * 16 + (lid >> 2);
            #pragma unroll
            for (int f = 0; f < 8; f++) {
                int cc = wc * 64 + f * 8 + 2 * (lid & 3);
                float bb0 = sf[EF_B1 + cc], bb1 = sf[EF_B1 + cc + 1];
                sf[EF_H + r0 * 132 + cc]       = tf32f(fmaxf(acc[f][0] + bb0, 0.f));
                sf[EF_H + r0 * 132 + cc + 1]   = tf32f(fmaxf(acc[f][1] + bb1, 0.f));
                sf[EF_H + (r0 + 8) * 132 + cc]     = tf32f(fmaxf(acc[f][2] + bb0, 0.f));
                sf[EF_H + (r0 + 8) * 132 + cc + 1] = tf32f(fmaxf(acc[f][3] + bb1, 0.f));
            }
        }
        __syncthreads();

        // GEMM2: [64x128] @ [128x64]
        float acc2[4][4];
        #pragma unroll
        for (int f = 0; f < 4; f++)
            #pragma unroll
            for (int j = 0; j < 4; j++) acc2[f][j] = 0.f;

        {
            const int ar = wr * 16 + (lid >> 2);
            #pragma unroll 4
            for (int sg = 0; sg < 16; sg++) {
                const int k = sg * 8 + (lid & 3);
                uint32_t a0 = __float_as_uint(sf[EF_H + ar * 132 + k]);
                uint32_t a1 = __float_as_uint(sf[EF_H + (ar + 8) * 132 + k]);
                uint32_t a2 = __float_as_uint(sf[EF_H + ar * 132 + k + 4]);
                uint32_t a3 = __float_as_uint(sf[EF_H + (ar + 8) * 132 + k + 4]);
                #pragma unroll
                for (int f = 0; f < 4; f++) {
                    float2 bp = *(const float2*)(sf + EF_W2P +
                        ((sg * 8 + wc * 4 + f) * 32 + lid) * 2);
                    mma_tf32(acc2[f], a0, a1, a2, a3,
                             __float_as_uint(bp.x), __float_as_uint(bp.y));
                }
            }
        }

        // epilogue2: bias + atomic scatter
        {
            const int r0 = wr * 16 + (lid >> 2);
            const int s0 = sSnk[r0], s1 = sSnk[r0 + 8];
            #pragma unroll
            for (int f = 0; f < 4; f++) {
                int cc = wc * 32 + f * 8 + 2 * (lid & 3);
                float bb0 = sf[EF_B2 + cc], bb1 = sf[EF_B2 + cc + 1];
                atomicAdd(inc + (size_t)s0 * NM + cc,     acc2[f][0] + bb0);
                atomicAdd(inc + (size_t)s0 * NM + cc + 1, acc2[f][1] + bb1);
                atomicAdd(inc + (size_t)s1 * NM + cc,     acc2[f][2] + bb0);
                atomicAdd(inc + (size_t)s1 * NM + cc + 1, acc2[f][3] + bb1);
            }
        }
        __syncthreads();   // protect sSrc/sSnk/H before next tile
    }
}

// =====================================================================
// Node kernel (persistent, tf32 mma.sync)
//   ninp[64n x 192] = [incoming(64) | states(128)] @ w1n -> relu -> @ w2n(126)
// smem floats:
//   NF_W1P [0,24576)      [24 ks][16 nf][32][2]
//   NF_W2P [24576,40960)  [16 ks][16 nf][32][2]  (cols 126,127 zero)
//   NF_A   [40960,45568)  2 bufs [64][36]
//   NF_H   [45568,54016)  [64][132]
//   NF_B1  54016 (128), NF_B2 54144 (128, padded)
// =====================================================================
#define NF_W1P 0
#define NF_W2P 24576
#define NF_A   40960
#define NF_H   45568
#define NF_B1  54016
#define NF_B2  54144
#define NODE_SMEM_BYTES ((54272) * 4)   // 217088

__global__ __launch_bounds__(256, 1) void node_kernel(
    const float* __restrict__ w1, const float* __restrict__ b1,
    const float* __restrict__ w2, const float* __restrict__ b2)
{
    extern __shared__ float sf[];
    const int tid = threadIdx.x;
    const int lid = tid & 31;
    const int wid = tid >> 5;
    const int wr = wid & 3;
    const int wc = wid >> 2;

    for (int i = tid; i < 24 * 16 * 32; i += 256) {
        int s = i >> 9, f = (i >> 5) & 15, l = i & 31;
        int k = s * 8 + (l & 3), n = f * 8 + (l >> 2);
        float2 p;
        p.x = tf32f(w1[k * NH + n]);
        p.y = tf32f(w1[(k + 4) * NH + n]);
        *(float2*)(sf + NF_W1P + 2 * i) = p;
    }
    for (int i = tid; i < 16 * 16 * 32; i += 256) {
        int s = i >> 9, f = (i >> 5) & 15, l = i & 31;
        int k = s * 8 + (l & 3), n = f * 8 + (l >> 2);
        float2 p;
        p.x = (n < NU) ? tf32f(w2[k * NU + n]) : 0.f;
        p.y = (n < NU) ? tf32f(w2[(k + 4) * NU + n]) : 0.f;
        *(float2*)(sf + NF_W2P + 2 * i) = p;
    }
    if (tid < NH) sf[NF_B1 + tid] = b1[tid];
    if (tid < 128) sf[NF_B2 + tid] = (tid < NU) ? b2[tid] : 0.f;
    __syncthreads();

    for (int T = blockIdx.x; T < NT_NODE_TOT; T += gridDim.x) {
        const int b = T / NT_NODE_B;
        const int n0 = (T - b * NT_NODE_B) * 64;
        float* st = g_states + (size_t)b * NN * ND;
        const float* inc = g_incoming + (size_t)b * NN * NM;

        float acc[8][4];
        #pragma unroll
        for (int f = 0; f < 8; f++)
            #pragma unroll
            for (int j = 0; j < 4; j++) acc[f][j] = 0.f;

        float r[8];
        // gather chunk 0 (incoming cols 0..31)
        {
            const int eb = wid * 8;
            #pragma unroll
            for (int i = 0; i < 8; i++) {
                int node = n0 + eb + i;
                r[i] = (node < NN) ? inc[(size_t)node * NM + lid] : 0.f;
            }
            #pragma unroll
            for (int i = 0; i < 8; i++)
                sf[NF_A + (eb + i) * 36 + lid] = tf32f(r[i]);
        }
        __syncthreads();

        #pragma unroll 1
        for (int c = 0; c < 6; c++) {
            if (c < 5) {
                const int cc = c + 1;
                #pragma unroll
                for (int i = 0; i < 8; i++) {
                    int node = n0 + wid * 8 + i;
                    float v = 0.f;
                    if (node < NN) {
                        int g = cc * 32 + lid;
                        v = (g < NM) ? inc[(size_t)node * NM + g]
                                     : st[(size_t)node * ND + g - NM];
                    }
                    r[i] = v;
                }
            }
            const float* A = sf + NF_A + (c & 1) * 2304;
            const int ar = wr * 16 + (lid >> 2);
            #pragma unroll
            for (int ks = 0; ks < 4; ks++) {
                const int k = ks * 8 + (lid & 3);
                uint32_t a0 = __float_as_uint(A[ar * 36 + k]);
                uint32_t a1 = __float_as_uint(A[(ar + 8) * 36 + k]);
                uint32_t a2 = __float_as_uint(A[ar * 36 + k + 4]);
                uint32_t a3 = __float_as_uint(A[(ar + 8) * 36 + k + 4]);
                const int sg = c * 4 + ks;
                #pragma unroll
                for (int f = 0; f < 8; f++) {
                    float2 bp = *(const float2*)(sf + NF_W1P +
                        ((sg * 16 + wc * 8 + f) * 32 + lid) * 2);
                    mma_tf32(acc[f], a0, a1, a2, a3,
                             __float_as_uint(bp.x), __float_as_uint(bp.y));
                }
            }
            if (c < 5) {
                float* dst = sf + NF_A + ((c + 1) & 1) * 2304;
                #pragma unroll
                for (int i = 0; i < 8; i++)
                    dst[(wid * 8 + i) * 36 + lid] = tf32f(r[i]);
            }
            __syncthreads();
        }

        // epilogue1: bias + relu -> H
        {
            const int r0 = wr * 16 + (lid >> 2);
            #pragma unroll
            for (int f = 0; f < 8; f++) {
                int cc = wc * 64 + f * 8 + 2 * (lid & 3);
                float bb0 = sf[NF_B1 + cc], bb1 = sf[NF_B1 + cc + 1];
                sf[NF_H + r0 * 132 + cc]       = tf32f(fmaxf(acc[f][0] + bb0, 0.f));
                sf[NF_H + r0 * 132 + cc + 1]   = tf32f(fmaxf(acc[f][1] + bb1, 0.f));
                sf[NF_H + (r0 + 8) * 132 + cc]     = tf32f(fmaxf(acc[f][2] + bb0, 0.f));
                sf[NF_H + (r0 + 8) * 132 + cc + 1] = tf32f(fmaxf(acc[f][3] + bb1, 0.f));
            }
        }
        __syncthreads();

        // GEMM2: [64x128] @ [128x128(padded 126)]
        float acc2[8][4];
        #pragma unroll
        for (int f = 0; f < 8; f++)
            #pragma unroll
            for (int j = 0; j < 4; j++) acc2[f][j] = 0.f;

        {
            const int ar = wr * 16 + (lid >> 2);
            #pragma unroll 4
            for (int sg = 0; sg < 16; sg++) {
                const int k = sg * 8 + (lid & 3);
                uint32_t a0 = __float_as_uint(sf[NF_H + ar * 132 + k]);
                uint32_t a1 = __float_as_uint(sf[NF_H + (ar + 8) * 132 + k]);
                uint32_t a2 = __float_as_uint(sf[NF_H + ar * 132 + k + 4]);
                uint32_t a3 = __float_as_uint(sf[NF_H + (ar + 8) * 132 + k + 4]);
                #pragma unroll
                for (int f = 0; f < 8; f++) {
                    float2 bp = *(const float2*)(sf + NF_W2P +
                        ((sg * 16 + wc * 8 + f) * 32 + lid) * 2);
                    mma_tf32(acc2[f], a0, a1, a2, a3,
                             __float_as_uint(bp.x), __float_as_uint(bp.y));
                }
            }
        }

        // epilogue2: in-place state update (exclusive ownership)
        {
            const int r0 = wr * 16 + (lid >> 2);
            const int node0 = n0 + r0, node1 = n0 + r0 + 8;
            #pragma unroll
            for (int f = 0; f < 8; f++) {
                int cc = wc * 64 + f * 8 + 2 * (lid & 3);
                float bb0 = sf[NF_B2 + cc], bb1 = sf[NF_B2 + cc + 1];
                if (node0 < NN) {
                    float* d = st + (size_t)node0 * ND + (ND - NU);
                    if (cc < NU)     d[cc]     += acc2[f][0] + bb0;
                    if (cc + 1 < NU) d[cc + 1] += acc2[f][1] + bb1;
                }
                if (node1 < NN) {
                    float* d = st + (size_t)node1 * ND + (ND - NU);
                    if (cc < NU)     d[cc]     += acc2[f][2] + bb0;
                    if (cc + 1 < NU) d[cc + 1] += acc2[f][3] + bb1;
                }
            }
        }
        __syncthreads();
    }
}

// =====================================================================
// Readout (fp32, unchanged)
// =====================================================================
#define EXT_SMEM_FLOATS (32 * 68 + 64 * 132)
#define NSPLIT 8
#define NCHUNK (NN / NSPLIT)   // 1250

__global__ __launch_bounds__(256) void extract_kernel(
    const float* __restrict__ attn, float* __restrict__ out)
{
    extern __shared__ float sm[];
    float* sAt = sm;            // [32][68]
    float* sS  = sm + 32 * 68;  // [64][132]

    const int tid = threadIdx.x;
    const int b = blockIdx.z, qt = blockIdx.y, ns = blockIdx.x;
    const int q0 = qt * 32;
    const int nbeg = ns * NCHUNK;
    const int nend = nbeg + NCHUNK;
    const float* st = g_states + (size_t)b * NN * ND;
    const float* at = attn + ((size_t)b * NQ + q0) * NN;

    const int tc = tid & 15;
    const int tr = tid >> 4;

    float acc[2][8];
    #pragma unroll
    for (int i = 0; i < 2; i++)
        #pragma unroll
        for (int j = 0; j < 8; j++) acc[i][j] = 0.f;

    for (int n0 = nbeg; n0 < nend; n0 += 64) {
        __syncthreads();
        #pragma unroll
        for (int t = 0; t < 8; t++) {
            int idx = tid + t * 256;
            int q = idx >> 6, nn = idx & 63;
            int n = n0 + nn;
            sAt[q * 68 + nn] = (n < nend) ? at[q * NN + n] : 0.f;
        }
        #pragma unroll
        for (int t = 0; t < 32; t++) {
            int idx = tid + t * 256;
            int nn = idx >> 7, d = idx & 127;
            int n = n0 + nn;
            sS[nn * 132 + d] = (n < nend) ? st[n * ND + d] : 0.f;
        }
        __syncthreads();
        #pragma unroll 8
        for (int nn = 0; nn < 64; nn++) {
            float4 bv0 = *(const float4*)&sS[nn * 132 + tc * 8];
            float4 bv1 = *(const float4*)&sS[nn * 132 + tc * 8 + 4];
            float bb[8] = {bv0.x, bv0.y, bv0.z, bv0.w, bv1.x, bv1.y, bv1.z, bv1.w};
            float a0 = sAt[(tr * 2 + 0) * 68 + nn];
            float a1 = sAt[(tr * 2 + 1) * 68 + nn];
            #pragma unroll
            for (int j = 0; j < 8; j++) {
                acc[0][j] = fmaf(a0, bb[j], acc[0][j]);
                acc[1][j] = fmaf(a1, bb[j], acc[1][j]);
            }
        }
    }

    #pragma unroll
    for (int i = 0; i < 2; i++) {
        int q = q0 + tr * 2 + i;
        float* drow = out + ((size_t)(b * NQ + q)) * OUTC + NP + tc * 8;
        #pragma unroll
        for (int j = 0; j < 8; j++) atomicAdd(drow + j, acc[i][j]);
    }
}

// =====================================================================
extern "C" void kernel_launch(void* const* d_in, const int* in_sizes, int n_in,
                              void* d_out, int out_size)
{
    const float* nodes = (const float*)d_in[0];
    const float* poses = (const float*)d_in[1];
    const float* attn  = (const float*)d_in[2];
    const int*   esrc  = (const int*)d_in[3];
    const int*   esnk  = (const int*)d_in[4];
    const float* w1e   = (const float*)d_in[5];
    const float* b1e   = (const float*)d_in[6];
    const float* w2e   = (const float*)d_in[7];
    const float* b2e   = (const float*)d_in[8];
    const float* w1n   = (const float*)d_in[9];
    const float* b1n   = (const float*)d_in[10];
    const float* w2n   = (const float*)d_in[11];
    const float* b2n   = (const float*)d_in[12];
    float* out = (float*)d_out;

    cudaFuncSetAttribute(edge_kernel, cudaFuncAttributeMaxDynamicSharedMemorySize,
                         EDGE_SMEM_BYTES);
    cudaFuncSetAttribute(node_kernel, cudaFuncAttributeMaxDynamicSharedMemorySize,
                         NODE_SMEM_BYTES);

    copy_states_kernel<<<(NB * NN * ND / 4 + 255) / 256, 256>>>(nodes);
    for (int s = 0; s < 3; s++) {
        zero_incoming_kernel<<<(NB * NN * NM / 4 + 255) / 256, 256>>>();
        edge_kernel<<<148, 256, EDGE_SMEM_BYTES>>>(esrc, esnk, w1e, b1e, w2e, b2e);
        node_kernel<<<148, 256, NODE_SMEM_BYTES>>>(w1n, b1n, w2n, b2n);
    }
    init_out_kernel<<<(NB * NQ * OUTC + 255) / 256, 256>>>(poses, out);
    extract_kernel<<<dim3(NSPLIT, NQ / 32, NB), 256, EXT_SMEM_FLOATS * 4>>>(attn, out);
}

// round 5
// speedup vs baseline: 3.4068x; 1.0539x over previous
#include <cuda_runtime.h>
#include <cuda_fp16.h>
#include <cstdint>

#define NB 4
#define NN 10000
#define NE 160000
#define NQ 256
#define ND 128
#define NM 64
#define NU 126
#define NH 128
#define NP 7
#define OUTC (NP + ND)   // 135
#define TE 64            // edges per tile
#define NTILES_B (NE / TE)        // 2500
#define NTILES_TOT (NTILES_B * NB)
#define NT_NODE_B 157             // ceil(10000/64)
#define NT_NODE_TOT (NT_NODE_B * NB)

// -------- scratch (static device globals: allocation-free) --------
__device__ float g_states[NB * NN * ND];     // 20.5 MB
__device__ float g_incoming[NB * NN * NM];   // 10.2 MB

// ============================ helpers ============================
__device__ __forceinline__ uint32_t pack_h2(float a, float b) {
    __half2 h = __floats2half2_rn(a, b);    // .x (low) = a, .y (high) = b
    return *reinterpret_cast<uint32_t*>(&h);
}
// D += A(16x16) * B(16x8), fp16 inputs, f32 accum
__device__ __forceinline__ void mma_f16(float* c, uint32_t a0, uint32_t a1,
                                        uint32_t a2, uint32_t a3,
                                        uint32_t b0, uint32_t b1) {
    asm volatile(
        "mma.sync.aligned.m16n8k16.row.col.f32.f16.f16.f32 "
        "{%0,%1,%2,%3}, {%4,%5,%6,%7}, {%8,%9}, {%0,%1,%2,%3};"
        : "+f"(c[0]), "+f"(c[1]), "+f"(c[2]), "+f"(c[3])
        : "r"(a0), "r"(a1), "r"(a2), "r"(a3), "r"(b0), "r"(b1));
}

// -------- utility kernels --------
__global__ void copy_states_kernel(const float* __restrict__ src) {
    int i = blockIdx.x * blockDim.x + threadIdx.x;
    const int n = NB * NN * ND / 4;
    if (i < n) reinterpret_cast<float4*>(g_states)[i] =
        reinterpret_cast<const float4*>(src)[i];
}

__global__ void zero_incoming_kernel() {
    int i = blockIdx.x * blockDim.x + threadIdx.x;
    const int n = NB * NN * NM / 4;
    if (i < n) reinterpret_cast<float4*>(g_incoming)[i] = make_float4(0.f, 0.f, 0.f, 0.f);
}

__global__ void init_out_kernel(const float* __restrict__ poses, float* __restrict__ out) {
    int i = blockIdx.x * blockDim.x + threadIdx.x;
    const int n = NB * NQ * OUTC;
    if (i < n) {
        int r = i / OUTC, c = i - r * OUTC;
        out[i] = (c < NP) ? poses[r * NP + c] : 0.f;
    }
}

// =====================================================================
// Edge kernel (persistent, fp16 mma m16n8k16, 2 CTAs/SM)
// smem (u32 units):
//   EW1 [0,16384)      W1 frags [16 ks][16 nf][32 lane][2]
//   EW2 [16384,20480)  W2 frags [ 8 ks][ 8 nf][32 lane][2]
//   EA  [20480,23040)  A chunk 2 bufs x [64 rows][20]
//   EH  [23040,27392)  H [64 rows][68]
//   EB1 27392 (128 f32), EB2 27520 (64), ESRC 27584, ESNK 27648 ... end 27712
// =====================================================================
#define EW1 0
#define EW2 16384
#define EA  20480
#define EH  23040
#define EB1 27392
#define EB2 27520
#define ESRC 27584
#define ESNK 27648
#define EDGE_SMEM_BYTES (27712 * 4)   // 110848

__global__ __launch_bounds__(256, 2) void edge_kernel(
    const int* __restrict__ esrc, const int* __restrict__ esnk,
    const float* __restrict__ w1, const float* __restrict__ b1,
    const float* __restrict__ w2, const float* __restrict__ b2)
{
    extern __shared__ uint32_t su[];
    float* sfB1 = (float*)(su + EB1);
    float* sfB2 = (float*)(su + EB2);
    int* sSrc = (int*)(su + ESRC);
    int* sSnk = (int*)(su + ESNK);

    const int tid = threadIdx.x;
    const int lid = tid & 31;
    const int wid = tid >> 5;
    const int wr = wid & 3;   // 16-edge row group
    const int wc = wid >> 2;  // column half

    // ---- stage permuted fp16 weight fragments ----
    for (int i = tid; i < 16 * 16 * 32; i += 256) {
        int s = i >> 9, f = (i >> 5) & 15, l = i & 31;
        int k = s * 16 + (l & 3) * 2, n = f * 8 + (l >> 2);
        uint2 v;
        v.x = pack_h2(w1[k * NH + n],       w1[(k + 1) * NH + n]);
        v.y = pack_h2(w1[(k + 8) * NH + n], w1[(k + 9) * NH + n]);
        *(uint2*)(su + EW1 + 2 * i) = v;
    }
    for (int i = tid; i < 8 * 8 * 32; i += 256) {
        int s = i >> 8, f = (i >> 5) & 7, l = i & 31;
        int k = s * 16 + (l & 3) * 2, n = f * 8 + (l >> 2);
        uint2 v;
        v.x = pack_h2(w2[k * NM + n],       w2[(k + 1) * NM + n]);
        v.y = pack_h2(w2[(k + 8) * NM + n], w2[(k + 9) * NM + n]);
        *(uint2*)(su + EW2 + 2 * i) = v;
    }
    if (tid < NH) sfB1[tid] = b1[tid];
    if (tid < NM) sfB2[tid] = b2[tid];
    __syncthreads();

    const int l16 = lid & 15;
    const int rhalf = lid >> 4;   // 0/1: which of the 2 rows this half-warp loads

    for (int T = blockIdx.x; T < NTILES_TOT; T += gridDim.x) {
        const int b = T / NTILES_B;
        const int e0 = (T - b * NTILES_B) * TE;
        const float* st = g_states + (size_t)b * NN * ND;
        float* inc = g_incoming + (size_t)b * NN * NM;

        if (tid < TE) sSrc[tid] = esrc[e0 + tid];
        else if (tid < 2 * TE) sSnk[tid - TE] = esnk[e0 + tid - TE];
        __syncthreads();

        float acc[8][4];
        #pragma unroll
        for (int f = 0; f < 8; f++)
            #pragma unroll
            for (int j = 0; j < 4; j++) acc[f][j] = 0.f;

        float2 r[4];
        // gather chunk 0 (src, cols 0..31): warp covers rows wid*8..+8
        {
            #pragma unroll
            for (int i = 0; i < 4; i++) {
                int row = wid * 8 + 2 * i + rhalf;
                r[i] = *(const float2*)&st[(size_t)sSrc[row] * ND + l16 * 2];
            }
            #pragma unroll
            for (int i = 0; i < 4; i++) {
                int row = wid * 8 + 2 * i + rhalf;
                su[EA + row * 20 + l16] = pack_h2(r[i].x, r[i].y);
            }
        }
        __syncthreads();

        const int ar = wr * 16 + (lid >> 2);
        #pragma unroll 1
        for (int c = 0; c < 8; c++) {
            if (c < 7) {                       // prefetch chunk c+1
                const int cc = c + 1;
                const int* nodes = (cc < 4) ? sSrc : sSnk;
                const int gk = (cc & 3) * 32 + l16 * 2;
                #pragma unroll
                for (int i = 0; i < 4; i++) {
                    int row = wid * 8 + 2 * i + rhalf;
                    r[i] = *(const float2*)&st[(size_t)nodes[row] * ND + gk];
                }
            }
            // compute chunk c: 2 ksteps of k16
            const uint32_t* A = su + EA + (c & 1) * 1280;
            #pragma unroll
            for (int ks = 0; ks < 2; ks++) {
                const int kw = ks * 8 + (lid & 3);
                uint32_t a0 = A[ar * 20 + kw];
                uint32_t a1 = A[(ar + 8) * 20 + kw];
                uint32_t a2 = A[ar * 20 + kw + 4];
                uint32_t a3 = A[(ar + 8) * 20 + kw + 4];
                const int sg = c * 2 + ks;
                #pragma unroll
                for (int f = 0; f < 8; f++) {
                    uint2 bp = *(const uint2*)(su + EW1 +
                        ((sg * 16 + wc * 8 + f) * 32 + lid) * 2);
                    mma_f16(acc[f], a0, a1, a2, a3, bp.x, bp.y);
                }
            }
            if (c < 7) {
                uint32_t* dst = su + EA + ((c + 1) & 1) * 1280;
                #pragma unroll
                for (int i = 0; i < 4; i++) {
                    int row = wid * 8 + 2 * i + rhalf;
                    dst[row * 20 + l16] = pack_h2(r[i].x, r[i].y);
                }
            }
            __syncthreads();
        }

        // epilogue1: bias + relu -> H (fp16 pairs)
        {
            const int r0 = wr * 16 + (lid >> 2);
            #pragma unroll
            for (int f = 0; f < 8; f++) {
                int n0 = wc * 64 + f * 8 + 2 * (lid & 3);
                float bb0 = sfB1[n0], bb1 = sfB1[n0 + 1];
                int wcol = wc * 32 + f * 4 + (lid & 3);
                su[EH + r0 * 68 + wcol] =
                    pack_h2(fmaxf(acc[f][0] + bb0, 0.f), fmaxf(acc[f][1] + bb1, 0.f));
                su[EH + (r0 + 8) * 68 + wcol] =
                    pack_h2(fmaxf(acc[f][2] + bb0, 0.f), fmaxf(acc[f][3] + bb1, 0.f));
            }
        }
        __syncthreads();

        // GEMM2: [64x128] @ [128x64]
        float acc2[4][4];
        #pragma unroll
        for (int f = 0; f < 4; f++)
            #pragma unroll
            for (int j = 0; j < 4; j++) acc2[f][j] = 0.f;

        #pragma unroll 2
        for (int ks = 0; ks < 8; ks++) {
            const int kw = ks * 8 + (lid & 3);
            uint32_t a0 = su[EH + ar * 68 + kw];
            uint32_t a1 = su[EH + (ar + 8) * 68 + kw];
            uint32_t a2 = su[EH + ar * 68 + kw + 4];
            uint32_t a3 = su[EH + (ar + 8) * 68 + kw + 4];
            #pragma unroll
            for (int f = 0; f < 4; f++) {
                uint2 bp = *(const uint2*)(su + EW2 +
                    ((ks * 8 + wc * 4 + f) * 32 + lid) * 2);
                mma_f16(acc2[f], a0, a1, a2, a3, bp.x, bp.y);
            }
        }

        // epilogue2: bias + atomic scatter
        {
            const int r0 = wr * 16 + (lid >> 2);
            const int s0 = sSnk[r0], s1 = sSnk[r0 + 8];
            #pragma unroll
            for (int f = 0; f < 4; f++) {
                int cc = wc * 32 + f * 8 + 2 * (lid & 3);
                float bb0 = sfB2[cc], bb1 = sfB2[cc + 1];
                atomicAdd(inc + (size_t)s0 * NM + cc,     acc2[f][0] + bb0);
                atomicAdd(inc + (size_t)s0 * NM + cc + 1, acc2[f][1] + bb1);
                atomicAdd(inc + (size_t)s1 * NM + cc,     acc2[f][2] + bb0);
                atomicAdd(inc + (size_t)s1 * NM + cc + 1, acc2[f][3] + bb1);
            }
        }
        __syncthreads();
    }
}

// =====================================================================
// Node kernel (persistent, fp16 mma, 2 CTAs/SM)
// smem (u32):
//   NW1 [0,12288)      [12 ks][16 nf][32][2]
//   NW2 [12288,20480)  [ 8 ks][16 nf][32][2]  (cols >=126 zero)
//   NA  [20480,23040)  2 x [64][20]
//   NH  [23040,27392)  [64][68]
//   NB1 27392 (128), NB2 27520 (128) ... end 27648
// =====================================================================
#define NW1 0
#define NW2 12288
#define NA  20480
#define NHS 23040
#define NB1 27392
#define NB2 27520
#define NODE_SMEM_BYTES (27648 * 4)   // 110592

__global__ __launch_bounds__(256, 2) void node_kernel(
    const float* __restrict__ w1, const float* __restrict__ b1,
    const float* __restrict__ w2, const float* __restrict__ b2)
{
    extern __shared__ uint32_t su[];
    float* sfB1 = (float*)(su + NB1);
    float* sfB2 = (float*)(su + NB2);

    const int tid = threadIdx.x;
    const int lid = tid & 31;
    const int wid = tid >> 5;
    const int wr = wid & 3;
    const int wc = wid >> 2;

    for (int i = tid; i < 12 * 16 * 32; i += 256) {
        int s = i >> 9, f = (i >> 5) & 15, l = i & 31;
        int k = s * 16 + (l & 3) * 2, n = f * 8 + (l >> 2);
        uint2 v;
        v.x = pack_h2(w1[k * NH + n],       w1[(k + 1) * NH + n]);
        v.y = pack_h2(w1[(k + 8) * NH + n], w1[(k + 9) * NH + n]);
        *(uint2*)(su + NW1 + 2 * i) = v;
    }
    for (int i = tid; i < 8 * 16 * 32; i += 256) {
        int s = i >> 9, f = (i >> 5) & 15, l = i & 31;
        int k = s * 16 + (l & 3) * 2, n = f * 8 + (l >> 2);
        uint2 v;
        if (n < NU) {
            v.x = pack_h2(w2[k * NU + n],       w2[(k + 1) * NU + n]);
            v.y = pack_h2(w2[(k + 8) * NU + n], w2[(k + 9) * NU + n]);
        } else v.x = v.y = 0u;
        *(uint2*)(su + NW2 + 2 * i) = v;
    }
    if (tid < NH) sfB1[tid] = b1[tid];
    if (tid < 128) sfB2[tid] = (tid < NU) ? b2[tid] : 0.f;
    __syncthreads();

    const int l16 = lid & 15;
    const int rhalf = lid >> 4;

    for (int T = blockIdx.x; T < NT_NODE_TOT; T += gridDim.x) {
        const int b = T / NT_NODE_B;
        const int n0 = (T - b * NT_NODE_B) * 64;
        float* st = g_states + (size_t)b * NN * ND;
        const float* inc = g_incoming + (size_t)b * NN * NM;

        float acc[8][4];
        #pragma unroll
        for (int f = 0; f < 8; f++)
            #pragma unroll
            for (int j = 0; j < 4; j++) acc[f][j] = 0.f;

        float2 r[4];
        // gather chunk 0 (incoming cols 0..31)
        {
            #pragma unroll
            for (int i = 0; i < 4; i++) {
                int row = wid * 8 + 2 * i + rhalf;
                int node = n0 + row;
                r[i] = (node < NN) ? *(const float2*)&inc[(size_t)node * NM + l16 * 2]
                                   : make_float2(0.f, 0.f);
            }
            #pragma unroll
            for (int i = 0; i < 4; i++) {
                int row = wid * 8 + 2 * i + rhalf;
                su[NA + row * 20 + l16] = pack_h2(r[i].x, r[i].y);
            }
        }
        __syncthreads();

        const int ar = wr * 16 + (lid >> 2);
        #pragma unroll 1
        for (int c = 0; c < 6; c++) {
            if (c < 5) {
                const int cc = c + 1;
                const int g = cc * 32 + l16 * 2;
                #pragma unroll
                for (int i = 0; i < 4; i++) {
                    int row = wid * 8 + 2 * i + rhalf;
                    int node = n0 + row;
                    if (node < NN)
                        r[i] = (g < NM) ? *(const float2*)&inc[(size_t)node * NM + g]
                                        : *(const float2*)&st[(size_t)node * ND + g - NM];
                    else r[i] = make_float2(0.f, 0.f);
                }
            }
            const uint32_t* A = su + NA + (c & 1) * 1280;
            #pragma unroll
            for (int ks = 0; ks < 2; ks++) {
                const int kw = ks * 8 + (lid & 3);
                uint32_t a0 = A[ar * 20 + kw];
                uint32_t a1 = A[(ar + 8) * 20 + kw];
                uint32_t a2 = A[ar * 20 + kw + 4];
                uint32_t a3 = A[(ar + 8) * 20 + kw + 4];
                const int sg = c * 2 + ks;
                #pragma unroll
                for (int f = 0; f < 8; f++) {
                    uint2 bp = *(const uint2*)(su + NW1 +
                        ((sg * 16 + wc * 8 + f) * 32 + lid) * 2);
                    mma_f16(acc[f], a0, a1, a2, a3, bp.x, bp.y);
                }
            }
            if (c < 5) {
                uint32_t* dst = su + NA + ((c + 1) & 1) * 1280;
                #pragma unroll
                for (int i = 0; i < 4; i++) {
                    int row = wid * 8 + 2 * i + rhalf;
                    dst[row * 20 + l16] = pack_h2(r[i].x, r[i].y);
                }
            }
            __syncthreads();
        }

        // epilogue1: bias + relu -> H
        {
            const int r0 = wr * 16 + (lid >> 2);
            #pragma unroll
            for (int f = 0; f < 8; f++) {
                int nn0 = wc * 64 + f * 8 + 2 * (lid & 3);
                float bb0 = sfB1[nn0], bb1 = sfB1[nn0 + 1];
                int wcol = wc * 32 + f * 4 + (lid & 3);
                su[NHS + r0 * 68 + wcol] =
                    pack_h2(fmaxf(acc[f][0] + bb0, 0.f), fmaxf(acc[f][1] + bb1, 0.f));
                su[NHS + (r0 + 8) * 68 + wcol] =
                    pack_h2(fmaxf(acc[f][2] + bb0, 0.f), fmaxf(acc[f][3] + bb1, 0.f));
            }
        }
        __syncthreads();

        // GEMM2: [64x128] @ [128x128(padded 126)]
        float acc2[8][4];
        #pragma unroll
        for (int f = 0; f < 8; f++)
            #pragma unroll
            for (int j = 0; j < 4; j++) acc2[f][j] = 0.f;

        #pragma unroll 2
        for (int ks = 0; ks < 8; ks++) {
            const int kw = ks * 8 + (lid & 3);
            uint32_t a0 = su[NHS + ar * 68 + kw];
            uint32_t a1 = su[NHS + (ar + 8) * 68 + kw];
            uint32_t a2 = su[NHS + ar * 68 + kw + 4];
            uint32_t a3 = su[NHS + (ar + 8) * 68 + kw + 4];
            #pragma unroll
            for (int f = 0; f < 8; f++) {
                uint2 bp = *(const uint2*)(su + NW2 +
                    ((ks * 16 + wc * 8 + f) * 32 + lid) * 2);
                mma_f16(acc2[f], a0, a1, a2, a3, bp.x, bp.y);
            }
        }

        // epilogue2: in-place state update (exclusive ownership)
        {
            const int r0 = wr * 16 + (lid >> 2);
            const int node0 = n0 + r0, node1 = n0 + r0 + 8;
            #pragma unroll
            for (int f = 0; f < 8; f++) {
                int cc = wc * 64 + f * 8 + 2 * (lid & 3);
                float bb0 = sfB2[cc], bb1 = sfB2[cc + 1];
                if (node0 < NN) {
                    float* d = st + (size_t)node0 * ND + (ND - NU);
                    if (cc < NU)     d[cc]     += acc2[f][0] + bb0;
                    if (cc + 1 < NU) d[cc + 1] += acc2[f][1] + bb1;
                }
                if (node1 < NN) {
                    float* d = st + (size_t)node1 * ND + (ND - NU);
                    if (cc < NU)     d[cc]     += acc2[f][2] + bb0;
                    if (cc + 1 < NU) d[cc + 1] += acc2[f][3] + bb1;
                }
            }
        }
        __syncthreads();
    }
}

// =====================================================================
// Readout (fp32, unchanged)
// =====================================================================
#define EXT_SMEM_FLOATS (32 * 68 + 64 * 132)
#define NSPLIT 8
#define NCHUNK (NN / NSPLIT)   // 1250

__global__ __launch_bounds__(256) void extract_kernel(
    const float* __restrict__ attn, float* __restrict__ out)
{
    extern __shared__ float sm[];
    float* sAt = sm;            // [32][68]
    float* sS  = sm + 32 * 68;  // [64][132]

    const int tid = threadIdx.x;
    const int b = blockIdx.z, qt = blockIdx.y, ns = blockIdx.x;
    const int q0 = qt * 32;
    const int nbeg = ns * NCHUNK;
    const int nend = nbeg + NCHUNK;
    const float* st = g_states + (size_t)b * NN * ND;
    const float* at = attn + ((size_t)b * NQ + q0) * NN;

    const int tc = tid & 15;
    const int tr = tid >> 4;

    float acc[2][8];
    #pragma unroll
    for (int i = 0; i < 2; i++)
        #pragma unroll
        for (int j = 0; j < 8; j++) acc[i][j] = 0.f;

    for (int n0 = nbeg; n0 < nend; n0 += 64) {
        __syncthreads();
        #pragma unroll
        for (int t = 0; t < 8; t++) {
            int idx = tid + t * 256;
            int q = idx >> 6, nn = idx & 63;
            int n = n0 + nn;
            sAt[q * 68 + nn] = (n < nend) ? at[q * NN + n] : 0.f;
        }
        #pragma unroll
        for (int t = 0; t < 32; t++) {
            int idx = tid + t * 256;
            int nn = idx >> 7, d = idx & 127;
            int n = n0 + nn;
            sS[nn * 132 + d] = (n < nend) ? st[n * ND + d] : 0.f;
        }
        __syncthreads();
        #pragma unroll 8
        for (int nn = 0; nn < 64; nn++) {
            float4 bv0 = *(const float4*)&sS[nn * 132 + tc * 8];
            float4 bv1 = *(const float4*)&sS[nn * 132 + tc * 8 + 4];
            float bb[8] = {bv0.x, bv0.y, bv0.z, bv0.w, bv1.x, bv1.y, bv1.z, bv1.w};
            float a0 = sAt[(tr * 2 + 0) * 68 + nn];
            float a1 = sAt[(tr * 2 + 1) * 68 + nn];
            #pragma unroll
            for (int j = 0; j < 8; j++) {
                acc[0][j] = fmaf(a0, bb[j], acc[0][j]);
                acc[1][j] = fmaf(a1, bb[j], acc[1][j]);
            }
        }
    }

    #pragma unroll
    for (int i = 0; i < 2; i++) {
        int q = q0 + tr * 2 + i;
        float* drow = out + ((size_t)(b * NQ + q)) * OUTC + NP + tc * 8;
        #pragma unroll
        for (int j = 0; j < 8; j++) atomicAdd(drow + j, acc[i][j]);
    }
}

// =====================================================================
extern "C" void kernel_launch(void* const* d_in, const int* in_sizes, int n_in,
                              void* d_out, int out_size)
{
    const float* nodes = (const float*)d_in[0];
    const float* poses = (const float*)d_in[1];
    const float* attn  = (const float*)d_in[2];
    const int*   esrc  = (const int*)d_in[3];
    const int*   esnk  = (const int*)d_in[4];
    const float* w1e   = (const float*)d_in[5];
    const float* b1e   = (const float*)d_in[6];
    const float* w2e   = (const float*)d_in[7];
    const float* b2e   = (const float*)d_in[8];
    const float* w1n   = (const float*)d_in[9];
    const float* b1n   = (const float*)d_in[10];
    const float* w2n   = (const float*)d_in[11];
    const float* b2n   = (const float*)d_in[12];
    float* out = (float*)d_out;

    cudaFuncSetAttribute(edge_kernel, cudaFuncAttributeMaxDynamicSharedMemorySize,
                         EDGE_SMEM_BYTES);
    cudaFuncSetAttribute(node_kernel, cudaFuncAttributeMaxDynamicSharedMemorySize,
                         NODE_SMEM_BYTES);

    copy_states_kernel<<<(NB * NN * ND / 4 + 255) / 256, 256>>>(nodes);
    for (int s = 0; s < 3; s++) {
        zero_incoming_kernel<<<(NB * NN * NM / 4 + 255) / 256, 256>>>();
        edge_kernel<<<296, 256, EDGE_SMEM_BYTES>>>(esrc, esnk, w1e, b1e, w2e, b2e);
        node_kernel<<<296, 256, NODE_SMEM_BYTES>>>(w1n, b1n, w2n, b2n);
    }
    init_out_kernel<<<(NB * NQ * OUTC + 255) / 256, 256>>>(poses, out);
    extract_kernel<<<dim3(NSPLIT, NQ / 32, NB), 256, EXT_SMEM_FLOATS * 4>>>(attn, out);
}

// round 7
// speedup vs baseline: 6.3532x; 1.8649x over previous
#include <cuda_runtime.h>
#include <cuda_fp16.h>
#include <cstdint>

#define NB 4
#define NN 10000
#define NE 160000
#define NQ 256
#define ND 128
#define NM 64
#define NU 126
#define NH 128
#define NP 7
#define OUTC (NP + ND)   // 135

#define TEE 128                    // edges per edge-tile
#define NTE_B (NE / TEE)           // 1250
#define NTE_TOT (NTE_B * NB)       // 5000

#define NT_NODE_B 157              // ceil(10000/64)
#define NT_NODE_TOT (NT_NODE_B * NB)

// -------- scratch (static device globals: allocation-free) --------
__device__ float g_states[NB * NN * ND];                  // 20.5 MB
__device__ __align__(16) __half g_statesH[NB * NN * ND];  // 10.2 MB fp16 mirror
__device__ float g_incoming[NB * NN * NM];                // 10.2 MB
// CSR scratch
__device__ int g_count[NN];
__device__ int g_cur[NN];
__device__ int g_sortedSrc[NE];
__device__ int g_sortedSnk[NE];

// ============================ helpers ============================
__device__ __forceinline__ uint32_t smem_u32(const void* p) {
    uint32_t a;
    asm("{ .reg .u64 t; cvta.to.shared.u64 t, %1; cvt.u32.u64 %0, t; }"
        : "=r"(a) : "l"(p));
    return a;
}
__device__ __forceinline__ uint32_t pack_h2(float a, float b) {
    __half2 h = __floats2half2_rn(a, b);
    return *reinterpret_cast<uint32_t*>(&h);
}
__device__ __forceinline__ void mma_f16(float* c, uint32_t a0, uint32_t a1,
                                        uint32_t a2, uint32_t a3,
                                        uint32_t b0, uint32_t b1) {
    asm volatile(
        "mma.sync.aligned.m16n8k16.row.col.f32.f16.f16.f32 "
        "{%0,%1,%2,%3}, {%4,%5,%6,%7}, {%8,%9}, {%0,%1,%2,%3};"
        : "+f"(c[0]), "+f"(c[1]), "+f"(c[2]), "+f"(c[3])
        : "r"(a0), "r"(a1), "r"(a2), "r"(a3), "r"(b0), "r"(b1));
}
#define CP_ASYNC16(dst, src) \
    asm volatile("cp.async.cg.shared.global [%0], [%1], 16;" \
                 :: "r"(dst), "l"(src) : "memory")
#define CP_COMMIT() asm volatile("cp.async.commit_group;" ::: "memory")
#define CP_WAIT0()  asm volatile("cp.async.wait_group 0;" ::: "memory")

// -------- utility kernels --------
__global__ void copy_states_kernel(const float* __restrict__ src) {
    int i = blockIdx.x * blockDim.x + threadIdx.x;
    const int n = NB * NN * ND / 4;
    if (i < n) {
        float4 v = reinterpret_cast<const float4*>(src)[i];
        reinterpret_cast<float4*>(g_states)[i] = v;
        __half2* mh = reinterpret_cast<__half2*>(g_statesH);
        mh[2 * i]     = __floats2half2_rn(v.x, v.y);
        mh[2 * i + 1] = __floats2half2_rn(v.z, v.w);
    }
}

__global__ void zero_incoming_kernel() {
    int i = blockIdx.x * blockDim.x + threadIdx.x;
    const int n = NB * NN * NM / 4;
    if (i < n) reinterpret_cast<float4*>(g_incoming)[i] = make_float4(0.f, 0.f, 0.f, 0.f);
}

__global__ void init_out_kernel(const float* __restrict__ poses, float* __restrict__ out) {
    int i = blockIdx.x * blockDim.x + threadIdx.x;
    const int n = NB * NQ * OUTC;
    if (i < n) {
        int r = i / OUTC, c = i - r * OUTC;
        out[i] = (c < NP) ? poses[r * NP + c] : 0.f;
    }
}

// -------- CSR build (once per launch; graph static across steps/batches) ----
__global__ void csr_zero_kernel() {
    int i = blockIdx.x * blockDim.x + threadIdx.x;
    if (i < NN) g_count[i] = 0;
}
__global__ void csr_hist_kernel(const int* __restrict__ esnk) {
    int i = blockIdx.x * blockDim.x + threadIdx.x;
    if (i < NE) atomicAdd(&g_count[esnk[i]], 1);
}
__global__ void csr_scan_kernel() {
    __shared__ int part[1024];
    int t = threadIdx.x;
    int beg = t * 10;
    int end = beg + 10 < NN ? beg + 10 : NN;
    int s = 0;
    for (int i = beg; i < end; i++) s += g_count[i];
    part[t] = s;
    __syncthreads();
    for (int d = 1; d < 1024; d <<= 1) {
        int v = (t >= d) ? part[t - d] : 0;
        __syncthreads();
        part[t] += v;
        __syncthreads();
    }
    int base = (t > 0) ? part[t - 1] : 0;
    for (int i = beg; i < end; i++) {
        g_cur[i] = base;
        base += g_count[i];
    }
}
__global__ void csr_scatter_kernel(const int* __restrict__ esrc,
                                   const int* __restrict__ esnk) {
    int i = blockIdx.x * blockDim.x + threadIdx.x;
    if (i < NE) {
        int s = esnk[i];
        int p = atomicAdd(&g_cur[s], 1);
        g_sortedSrc[p] = esrc[i];
        g_sortedSnk[p] = s;
    }
}

// =====================================================================
// Edge kernel: persistent, 512 thr, 1 CTA/SM, fp16 mma, cp.async gather,
// sink-sorted edges + segmented-reduce scatter.
// smem (u32 units):
//   EW1 [0,16384)       W1 frags [16 sg][16 nf][32][2]        64 KB
//   EW2 [16384,20480)   W2 frags [ 8 sg][ 8 nf][32][2]        16 KB
//   EA  [20480,37376)   A tile [128 e][132 u32] (256 f16 + pad) 66 KB
//   EHH [37376,46080)   H [128 e][68 u32] (128 f16 + pad)     34 KB
//   EMS [46080,54784)   MSG [128 e][68 f32]                   34 KB
//   EB1 54784 (128 f32), EB2 54912 (64), ESNKB 54976 (2x128 int) -> 55232
// =====================================================================
#define EW1   0
#define EW2   16384
#define EA    20480
#define EHH   37376
#define EMS   46080
#define EB1   54784
#define EB2   54912
#define ESNKB 54976
#define EDGE_SMEM_BYTES (55232 * 4)   // 220928

__device__ __forceinline__ void issue_gather(uint32_t aBase, int eb,
                                             const __half* __restrict__ stH,
                                             int tid) {
    #pragma unroll
    for (int i = 0; i < 8; i++) {
        int idx = tid + i * 512;            // 0..4095
        int row = idx >> 4;                 // 0..255
        int ch  = idx & 15;                 // 16B chunk within 256B row
        int e   = row & 127;
        bool snk = row >= 128;
        int node = snk ? g_sortedSnk[eb + e] : g_sortedSrc[eb + e];
        uint32_t dst = aBase + (uint32_t)(e * 528 + (snk ? 256 : 0) + ch * 16);
        const void* src = (const void*)(stH + (size_t)node * ND + ch * 8);
        CP_ASYNC16(dst, src);
    }
}

__global__ __launch_bounds__(512, 1) void edge_kernel(
    const float* __restrict__ w1, const float* __restrict__ b1,
    const float* __restrict__ w2, const float* __restrict__ b2)
{
    extern __shared__ uint32_t su[];
    float* sfB1 = (float*)(su + EB1);
    float* sfB2 = (float*)(su + EB2);
    int* sSnkB = (int*)(su + ESNKB);

    const int tid = threadIdx.x;
    const int lid = tid & 31;
    const int wid = tid >> 5;          // 0..15
    const int wg  = wid >> 1;          // 8 row groups of 16 edges
    const int wc  = wid & 1;           // column half
    const uint32_t aBase = smem_u32(su + EA);

    // ---- prologue: issue tile-0 gather immediately (overlaps weight staging)
    {
        int T0 = blockIdx.x;
        int b0 = T0 / NTE_B;
        int eb0 = (T0 - b0 * NTE_B) * TEE;
        const __half* stH = g_statesH + (size_t)b0 * NN * ND;
        issue_gather(aBase, eb0, stH, tid);
        if (tid < TEE) sSnkB[tid] = g_sortedSnk[eb0 + tid];
    }
    CP_COMMIT();

    // ---- stage permuted fp16 weight fragments ----
    for (int i = tid; i < 16 * 16 * 32; i += 512) {
        int s = i >> 9, f = (i >> 5) & 15, l = i & 31;
        int k = s * 16 + (l & 3) * 2, n = f * 8 + (l >> 2);
        uint2 v;
        v.x = pack_h2(w1[k * NH + n],       w1[(k + 1) * NH + n]);
        v.y = pack_h2(w1[(k + 8) * NH + n], w1[(k + 9) * NH + n]);
        *(uint2*)(su + EW1 + 2 * i) = v;
    }
    for (int i = tid; i < 8 * 8 * 32; i += 512) {
        int s = i >> 8, f = (i >> 5) & 7, l = i & 31;
        int k = s * 16 + (l & 3) * 2, n = f * 8 + (l >> 2);
        uint2 v;
        v.x = pack_h2(w2[k * NM + n],       w2[(k + 1) * NM + n]);
        v.y = pack_h2(w2[(k + 8) * NM + n], w2[(k + 9) * NM + n]);
        *(uint2*)(su + EW2 + 2 * i) = v;
    }
    if (tid < NH) sfB1[tid] = b1[tid];
    else if (tid < NH + NM) sfB2[tid - NH] = b2[tid - NH];

    const int arq = wg * 16 + (lid >> 2);

    int it = 0;
    for (int T = blockIdx.x; T < NTE_TOT; T += gridDim.x, it++) {
        const int b = T / NTE_B;
        float* inc = g_incoming + (size_t)b * NN * NM;

        CP_WAIT0();
        __syncthreads();   // A tile + sSnk(buf it&1) ready; weights ready (it==0)

        // ---- GEMM1: [128e x 256k] @ [256k x 128h], full-tile, no barriers
        float acc[8][4];
        #pragma unroll
        for (int f = 0; f < 8; f++)
            #pragma unroll
            for (int j = 0; j < 4; j++) acc[f][j] = 0.f;

        #pragma unroll 4
        for (int sg = 0; sg < 16; sg++) {
            const int kw = sg * 8 + (lid & 3);
            uint32_t a0 = su[EA + arq * 132 + kw];
            uint32_t a1 = su[EA + (arq + 8) * 132 + kw];
            uint32_t a2 = su[EA + arq * 132 + kw + 4];
            uint32_t a3 = su[EA + (arq + 8) * 132 + kw + 4];
            #pragma unroll
            for (int f = 0; f < 8; f++) {
                uint2 bp = *(const uint2*)(su + EW1 +
                    ((sg * 16 + wc * 8 + f) * 32 + lid) * 2);
                mma_f16(acc[f], a0, a1, a2, a3, bp.x, bp.y);
            }
        }

        // ---- epilogue1: bias + relu -> H (fp16)
        #pragma unroll
        for (int f = 0; f < 8; f++) {
            int n0 = wc * 64 + f * 8 + 2 * (lid & 3);
            float bb0 = sfB1[n0], bb1 = sfB1[n0 + 1];
            int wcol = wc * 32 + f * 4 + (lid & 3);
            su[EHH + arq * 68 + wcol] =
                pack_h2(fmaxf(acc[f][0] + bb0, 0.f), fmaxf(acc[f][1] + bb1, 0.f));
            su[EHH + (arq + 8) * 68 + wcol] =
                pack_h2(fmaxf(acc[f][2] + bb0, 0.f), fmaxf(acc[f][3] + bb1, 0.f));
        }
        __syncthreads();   // H ready; A fully consumed -> safe to refill

        // ---- issue next tile's gather (latency hidden behind GEMM2+scatter)
        {
            int Tn = T + gridDim.x;
            if (Tn < NTE_TOT) {
                int bn = Tn / NTE_B;
                int ebn = (Tn - bn * NTE_B) * TEE;
                const __half* stH = g_statesH + (size_t)bn * NN * ND;
                issue_gather(aBase, ebn, stH, tid);
                if (tid < TEE)
                    sSnkB[((it + 1) & 1) * TEE + tid] = g_sortedSnk[ebn + tid];
            }
        }
        CP_COMMIT();

        // ---- GEMM2: [128e x 128h] @ [128h x 64m]
        float acc2[4][4];
        #pragma unroll
        for (int f = 0; f < 4; f++)
            #pragma unroll
            for (int j = 0; j < 4; j++) acc2[f][j] = 0.f;

        #pragma unroll 4
        for (int sg = 0; sg < 8; sg++) {
            const int kw = sg * 8 + (lid & 3);
            uint32_t a0 = su[EHH + arq * 68 + kw];
            uint32_t a1 = su[EHH + (arq + 8) * 68 + kw];
            uint32_t a2 = su[EHH + arq * 68 + kw + 4];
            uint32_t a3 = su[EHH + (arq + 8) * 68 + kw + 4];
            #pragma unroll
            for (int f = 0; f < 4; f++) {
                uint2 bp = *(const uint2*)(su + EW2 +
                    ((sg * 8 + wc * 4 + f) * 32 + lid) * 2);
                mma_f16(acc2[f], a0, a1, a2, a3, bp.x, bp.y);
            }
        }

        // ---- epilogue2: bias -> MSG (fp32)
        float* sfMSG = (float*)(su + EMS);
        #pragma unroll
        for (int f = 0; f < 4; f++) {
            int m = wc * 32 + f * 8 + 2 * (lid & 3);
            float bb0 = sfB2[m], bb1 = sfB2[m + 1];
            sfMSG[arq * 68 + m]           = acc2[f][0] + bb0;
            sfMSG[arq * 68 + m + 1]       = acc2[f][1] + bb1;
            sfMSG[(arq + 8) * 68 + m]     = acc2[f][2] + bb0;
            sfMSG[(arq + 8) * 68 + m + 1] = acc2[f][3] + bb1;
        }
        __syncthreads();   // MSG ready

        // ---- segmented reduction over sorted sinks + coalesced atomics
        {
            const int* sSnk = sSnkB + (it & 1) * TEE;
            const int c = tid & 63;        // msg channel
            const int s = tid >> 6;        // strip of 16 edges
            const int e0s = s * 16;
            float part = 0.f;
            int cur = sSnk[e0s];
            #pragma unroll
            for (int j = 0; j < 16; j++) {
                part += sfMSG[(e0s + j) * 68 + c];
                int nxt = (j < 15) ? sSnk[e0s + j + 1] : -1;
                if (nxt != cur) {          // uniform across warp (same edges)
                    atomicAdd(inc + (size_t)cur * NM + c, part);
                    part = 0.f;
                    cur = nxt;
                }
            }
        }
        // next iteration's top barrier orders MSG reuse
    }
}

// =====================================================================
// Node kernel (persistent, fp16 mma, 2 CTAs/SM) — unchanged except it now
// also maintains the fp16 state mirror.
// =====================================================================
#define NW1 0
#define NW2 12288
#define NA  20480
#define NHS 23040
#define NB1 27392
#define NB2 27520
#define NODE_SMEM_BYTES (27648 * 4)   // 110592

__global__ __launch_bounds__(256, 2) void node_kernel(
    const float* __restrict__ w1, const float* __restrict__ b1,
    const float* __restrict__ w2, const float* __restrict__ b2)
{
    extern __shared__ uint32_t su[];
    float* sfB1 = (float*)(su + NB1);
    float* sfB2 = (float*)(su + NB2);

    const int tid = threadIdx.x;
    const int lid = tid & 31;
    const int wid = tid >> 5;
    const int wr = wid & 3;
    const int wc = wid >> 2;

    for (int i = tid; i < 12 * 16 * 32; i += 256) {
        int s = i >> 9, f = (i >> 5) & 15, l = i & 31;
        int k = s * 16 + (l & 3) * 2, n = f * 8 + (l >> 2);
        uint2 v;
        v.x = pack_h2(w1[k * NH + n],       w1[(k + 1) * NH + n]);
        v.y = pack_h2(w1[(k + 8) * NH + n], w1[(k + 9) * NH + n]);
        *(uint2*)(su + NW1 + 2 * i) = v;
    }
    for (int i = tid; i < 8 * 16 * 32; i += 256) {
        int s = i >> 9, f = (i >> 5) & 15, l = i & 31;
        int k = s * 16 + (l & 3) * 2, n = f * 8 + (l >> 2);
        uint2 v;
        if (n < NU) {
            v.x = pack_h2(w2[k * NU + n],       w2[(k + 1) * NU + n]);
            v.y = pack_h2(w2[(k + 8) * NU + n], w2[(k + 9) * NU + n]);
        } else v.x = v.y = 0u;
        *(uint2*)(su + NW2 + 2 * i) = v;
    }
    if (tid < NH) sfB1[tid] = b1[tid];
    if (tid < 128) sfB2[tid] = (tid < NU) ? b2[tid] : 0.f;
    __syncthreads();

    const int l16 = lid & 15;
    const int rhalf = lid >> 4;

    for (int T = blockIdx.x; T < NT_NODE_TOT; T += gridDim.x) {
        const int b = T / NT_NODE_B;
        const int n0 = (T - b * NT_NODE_B) * 64;
        float* st = g_states + (size_t)b * NN * ND;
        __half* stH = g_statesH + (size_t)b * NN * ND;
        const float* inc = g_incoming + (size_t)b * NN * NM;

        float acc[8][4];
        #pragma unroll
        for (int f = 0; f < 8; f++)
            #pragma unroll
            for (int j = 0; j < 4; j++) acc[f][j] = 0.f;

        float2 r[4];
        {
            #pragma unroll
            for (int i = 0; i < 4; i++) {
                int row = wid * 8 + 2 * i + rhalf;
                int node = n0 + row;
                r[i] = (node < NN) ? *(const float2*)&inc[(size_t)node * NM + l16 * 2]
                                   : make_float2(0.f, 0.f);
            }
            #pragma unroll
            for (int i = 0; i < 4; i++) {
                int row = wid * 8 + 2 * i + rhalf;
                su[NA + row * 20 + l16] = pack_h2(r[i].x, r[i].y);
            }
        }
        __syncthreads();

        const int ar = wr * 16 + (lid >> 2);
        #pragma unroll 1
        for (int c = 0; c < 6; c++) {
            if (c < 5) {
                const int cc = c + 1;
                const int g = cc * 32 + l16 * 2;
                #pragma unroll
                for (int i = 0; i < 4; i++) {
                    int row = wid * 8 + 2 * i + rhalf;
                    int node = n0 + row;
                    if (node < NN)
                        r[i] = (g < NM) ? *(const float2*)&inc[(size_t)node * NM + g]
                                        : *(const float2*)&st[(size_t)node * ND + g - NM];
                    else r[i] = make_float2(0.f, 0.f);
                }
            }
            const uint32_t* A = su + NA + (c & 1) * 1280;
            #pragma unroll
            for (int ks = 0; ks < 2; ks++) {
                const int kw = ks * 8 + (lid & 3);
                uint32_t a0 = A[ar * 20 + kw];
                uint32_t a1 = A[(ar + 8) * 20 + kw];
                uint32_t a2 = A[ar * 20 + kw + 4];
                uint32_t a3 = A[(ar + 8) * 20 + kw + 4];
                const int sg = c * 2 + ks;
                #pragma unroll
                for (int f = 0; f < 8; f++) {
                    uint2 bp = *(const uint2*)(su + NW1 +
                        ((sg * 16 + wc * 8 + f) * 32 + lid) * 2);
                    mma_f16(acc[f], a0, a1, a2, a3, bp.x, bp.y);
                }
            }
            if (c < 5) {
                uint32_t* dst = su + NA + ((c + 1) & 1) * 1280;
                #pragma unroll
                for (int i = 0; i < 4; i++) {
                    int row = wid * 8 + 2 * i + rhalf;
                    dst[row * 20 + l16] = pack_h2(r[i].x, r[i].y);
                }
            }
            __syncthreads();
        }

        {
            #pragma unroll
            for (int f = 0; f < 8; f++) {
                int nn0 = wc * 64 + f * 8 + 2 * (lid & 3);
                float bb0 = sfB1[nn0], bb1 = sfB1[nn0 + 1];
                int wcol = wc * 32 + f * 4 + (lid & 3);
                su[NHS + ar * 68 + wcol] =
                    pack_h2(fmaxf(acc[f][0] + bb0, 0.f), fmaxf(acc[f][1] + bb1, 0.f));
                su[NHS + (ar + 8) * 68 + wcol] =
                    pack_h2(fmaxf(acc[f][2] + bb0, 0.f), fmaxf(acc[f][3] + bb1, 0.f));
            }
        }
        __syncthreads();

        float acc2[8][4];
        #pragma unroll
        for (int f = 0; f < 8; f++)
            #pragma unroll
            for (int j = 0; j < 4; j++) acc2[f][j] = 0.f;

        #pragma unroll 2
        for (int ks = 0; ks < 8; ks++) {
            const int kw = ks * 8 + (lid & 3);
            uint32_t a0 = su[NHS + ar * 68 + kw];
            uint32_t a1 = su[NHS + (ar + 8) * 68 + kw];
            uint32_t a2 = su[NHS + ar * 68 + kw + 4];
            uint32_t a3 = su[NHS + (ar + 8) * 68 + kw + 4];
            #pragma unroll
            for (int f = 0; f < 8; f++) {
                uint2 bp = *(const uint2*)(su + NW2 +
                    ((ks * 16 + wc * 8 + f) * 32 + lid) * 2);
                mma_f16(acc2[f], a0, a1, a2, a3, bp.x, bp.y);
            }
        }

        // in-place state update + fp16 mirror (exclusive row/col ownership)
        {
            const int node0 = n0 + ar, node1 = n0 + ar + 8;
            #pragma unroll
            for (int f = 0; f < 8; f++) {
                int cc = wc * 64 + f * 8 + 2 * (lid & 3);   // even, <= 126
                float bb0 = sfB2[cc], bb1 = sfB2[cc + 1];
                if (cc < NU) {   // cc even, NU even -> cc+1 < NU too
                    if (node0 < NN) {
                        float* d = st + (size_t)node0 * ND + 2;
                        float nv0 = d[cc] + acc2[f][0] + bb0;
                        float nv1 = d[cc + 1] + acc2[f][1] + bb1;
                        d[cc] = nv0; d[cc + 1] = nv1;
                        *(__half2*)(stH + (size_t)node0 * ND + 2 + cc) =
                            __floats2half2_rn(nv0, nv1);
                    }
                    if (node1 < NN) {
                        float* d = st + (size_t)node1 * ND + 2;
                        float nv0 = d[cc] + acc2[f][2] + bb0;
                        float nv1 = d[cc + 1] + acc2[f][3] + bb1;
                        d[cc] = nv0; d[cc + 1] = nv1;
                        *(__half2*)(stH + (size_t)node1 * ND + 2 + cc) =
                            __floats2half2_rn(nv0, nv1);
                    }
                }
            }
        }
        __syncthreads();
    }
}

// =====================================================================
// Readout (fp32, unchanged)
// =====================================================================
#define EXT_SMEM_FLOATS (32 * 68 + 64 * 132)
#define NSPLIT 8
#define NCHUNK (NN / NSPLIT)   // 1250

__global__ __launch_bounds__(256) void extract_kernel(
    const float* __restrict__ attn, float* __restrict__ out)
{
    extern __shared__ float sm[];
    float* sAt = sm;            // [32][68]
    float* sS  = sm + 32 * 68;  // [64][132]

    const int tid = threadIdx.x;
    const int b = blockIdx.z, qt = blockIdx.y, ns = blockIdx.x;
    const int q0 = qt * 32;
    const int nbeg = ns * NCHUNK;
    const int nend = nbeg + NCHUNK;
    const float* st = g_states + (size_t)b * NN * ND;
    const float* at = attn + ((size_t)b * NQ + q0) * NN;

    const int tc = tid & 15;
    const int tr = tid >> 4;

    float acc[2][8];
    #pragma unroll
    for (int i = 0; i < 2; i++)
        #pragma unroll
        for (int j = 0; j < 8; j++) acc[i][j] = 0.f;

    for (int n0 = nbeg; n0 < nend; n0 += 64) {
        __syncthreads();
        #pragma unroll
        for (int t = 0; t < 8; t++) {
            int idx = tid + t * 256;
            int q = idx >> 6, nn = idx & 63;
            int n = n0 + nn;
            sAt[q * 68 + nn] = (n < nend) ? at[q * NN + n] : 0.f;
        }
        #pragma unroll
        for (int t = 0; t < 32; t++) {
            int idx = tid + t * 256;
            int nn = idx >> 7, d = idx & 127;
            int n = n0 + nn;
            sS[nn * 132 + d] = (n < nend) ? st[n * ND + d] : 0.f;
        }
        __syncthreads();
        #pragma unroll 8
        for (int nn = 0; nn < 64; nn++) {
            float4 bv0 = *(const float4*)&sS[nn * 132 + tc * 8];
            float4 bv1 = *(const float4*)&sS[nn * 132 + tc * 8 + 4];
            float bb[8] = {bv0.x, bv0.y, bv0.z, bv0.w, bv1.x, bv1.y, bv1.z, bv1.w};
            float a0 = sAt[(tr * 2 + 0) * 68 + nn];
            float a1 = sAt[(tr * 2 + 1) * 68 + nn];
            #pragma unroll
            for (int j = 0; j < 8; j++) {
                acc[0][j] = fmaf(a0, bb[j], acc[0][j]);
                acc[1][j] = fmaf(a1, bb[j], acc[1][j]);
            }
        }
    }

    #pragma unroll
    for (int i = 0; i < 2; i++) {
        int q = q0 + tr * 2 + i;
        float* drow = out + ((size_t)(b * NQ + q)) * OUTC + NP + tc * 8;
        #pragma unroll
        for (int j = 0; j < 8; j++) atomicAdd(drow + j, acc[i][j]);
    }
}

// =====================================================================
extern "C" void kernel_launch(void* const* d_in, const int* in_sizes, int n_in,
                              void* d_out, int out_size)
{
    const float* nodes = (const float*)d_in[0];
    const float* poses = (const float*)d_in[1];
    const float* attn  = (const float*)d_in[2];
    const int*   esrc  = (const int*)d_in[3];
    const int*   esnk  = (const int*)d_in[4];
    const float* w1e   = (const float*)d_in[5];
    const float* b1e   = (const float*)d_in[6];
    const float* w2e   = (const float*)d_in[7];
    const float* b2e   = (const float*)d_in[8];
    const float* w1n   = (const float*)d_in[9];
    const float* b1n   = (const float*)d_in[10];
    const float* w2n   = (const float*)d_in[11];
    const float* b2n   = (const float*)d_in[12];
    float* out = (float*)d_out;

    cudaFuncSetAttribute(edge_kernel, cudaFuncAttributeMaxDynamicSharedMemorySize,
                         EDGE_SMEM_BYTES);
    cudaFuncSetAttribute(node_kernel, cudaFuncAttributeMaxDynamicSharedMemorySize,
                         NODE_SMEM_BYTES);

    copy_states_kernel<<<(NB * NN * ND / 4 + 255) / 256, 256>>>(nodes);

    // Build sink-sorted edge list (CSR) once; reused by all 3 steps.
    csr_zero_kernel<<<(NN + 255) / 256, 256>>>();
    csr_hist_kernel<<<(NE + 255) / 256, 256>>>(esnk);
    csr_scan_kernel<<<1, 1024>>>();
    csr_scatter_kernel<<<(NE + 255) / 256, 256>>>(esrc, esnk);

    for (int s = 0; s < 3; s++) {
        zero_incoming_kernel<<<(NB * NN * NM / 4 + 255) / 256, 256>>>();
        edge_kernel<<<148, 512, EDGE_SMEM_BYTES>>>(w1e, b1e, w2e, b2e);
        node_kernel<<<296, 256, NODE_SMEM_BYTES>>>(w1n, b1n, w2n, b2n);
    }
    init_out_kernel<<<(NB * NQ * OUTC + 255) / 256, 256>>>(poses, out);
    extract_kernel<<<dim3(NSPLIT, NQ / 32, NB), 256, EXT_SMEM_FLOATS * 4>>>(attn, out);
}